// round 6
// baseline (speedup 1.0000x reference)
#include <cuda_runtime.h>

// out[b,j,h] = (1/N) * sum_i sum_g W[b,i,j,h,g] * x[b,i,g]
// B=16, N=32, H=64. W: 256 MiB fp32 streamed once -> pure HBM-bound.
//
// R6: contiguous-read restructure. W layout is [b][i][j][h][g]; previous
// kernels fixed (b,j) and strode 512KB between 8-16KB chunks. Here each CTA
// fixes (b, i, j-half) and streams 256KB FULLY CONTIGUOUS, computing
// partial[b,i,j,h] = sum_g W[b,i,j,h,g] * x[b,i,g] into an 8MB scratch.
// Pass 2 reduces over i in fixed order (deterministic). Tests whether DRAM
// row/channel locality (not LTS, not latency-hiding) is the 18%-idle cause.

#define BB 16
#define NN 32
#define HH 64
#define TILE_F4 1024          // HH*HH/4 per (b,i,j) tile
#define JH 16                 // j's per CTA (half of NN)

__device__ float g_partial[BB * NN * NN * HH];   // 8 MB scratch

__global__ __launch_bounds__(256, 4)
void msg_pass1(const float4* __restrict__ W,
               const float4* __restrict__ X)
{
    const int blk = blockIdx.x;          // 0..1023
    const int bi  = blk >> 1;            // 0..511  (b*NN + i)
    const int jh  = blk & 1;             // j-half
    const int t   = threadIdx.x;         // 0..255

    const int g4 = t & 15;               // g-quad
    const int h0 = t >> 4;               // 0..15

    // x[b, i, 4*g4 : 4*g4+4] — one float4, reused for all j.
    const float4 xv = X[(size_t)bi * (HH / 4) + g4];

    // Contiguous run: W[b, i, jh*16 : jh*16+16, :, :] = 16 tiles * 16KB = 256KB
    const float4* Wb = W + ((size_t)bi * NN + jh * JH) * TILE_F4;
    float* pb = g_partial + ((size_t)bi * NN + jh * JH) * HH;

    const unsigned mask = 0xFFFFFFFFu;

    #pragma unroll 2
    for (int j = 0; j < JH; ++j) {
        const float4* tp = Wb + (size_t)j * TILE_F4;
        const float4 w0 = tp[t];
        const float4 w1 = tp[t + 256];
        const float4 w2 = tp[t + 512];
        const float4 w3 = tp[t + 768];

        float a0 = w0.x * xv.x + w0.y * xv.y + w0.z * xv.z + w0.w * xv.w;
        float a1 = w1.x * xv.x + w1.y * xv.y + w1.z * xv.z + w1.w * xv.w;
        float a2 = w2.x * xv.x + w2.y * xv.y + w2.z * xv.z + w2.w * xv.w;
        float a3 = w3.x * xv.x + w3.y * xv.y + w3.z * xv.z + w3.w * xv.w;

        #pragma unroll
        for (int off = 8; off > 0; off >>= 1) {
            a0 += __shfl_down_sync(mask, a0, off);
            a1 += __shfl_down_sync(mask, a1, off);
            a2 += __shfl_down_sync(mask, a2, off);
            a3 += __shfl_down_sync(mask, a3, off);
        }

        if (g4 == 0) {
            float* p = pb + (size_t)j * HH + h0;
            p[0]  = a0;
            p[16] = a1;
            p[32] = a2;
            p[48] = a3;
        }
    }
}

// out[b,j,h] = (1/N) * sum_i partial[b,i,j,h]   (fixed order -> deterministic)
__global__ __launch_bounds__(256)
void msg_pass2(float* __restrict__ out)
{
    const int idx = blockIdx.x * 256 + threadIdx.x;   // 0..32767
    const int b   = idx >> 11;                        // / (NN*HH)
    const int rem = idx & 2047;                       // j*HH + h

    const float* p = g_partial + (size_t)b * NN * NN * HH + rem;

    float s = 0.f;
    #pragma unroll
    for (int i = 0; i < NN; ++i)
        s += p[(size_t)i * NN * HH];

    out[idx] = s * (1.0f / (float)NN);
}

extern "C" void kernel_launch(void* const* d_in, const int* in_sizes, int n_in,
                              void* d_out, int out_size)
{
    const float4* W = (const float4*)d_in[0];   // edge_wgt [B,N,N,H,H] fp32
    const float4* X = (const float4*)d_in[1];   // node_hidden [B,N,H] fp32
    float* out = (float*)d_out;                 // [B,N,H] fp32

    msg_pass1<<<BB * NN * 2, 256>>>(W, X);      // 1024 CTAs, 256KB contiguous each
    msg_pass2<<<(BB * NN * HH) / 256, 256>>>(out);   // 128 CTAs
}

// round 7
// speedup vs baseline: 1.1805x; 1.1805x over previous
#include <cuda_runtime.h>

// out[b,j,h] = (1/N) * sum_i sum_g W[b,i,j,h,g] * x[b,i,g]
// B=16, N=32, H=64. W: 256 MiB fp32 streamed once -> pure HBM-bound.
//
// R7 = R1 champion body (4 LDG.128/thread/iter, one CTA per (b,j)) with
// per-CTA staggered i-start: CTA bj sweeps i = (k + bj) mod 32. All previous
// kernels swept i in lockstep, so at any instant 512 CTAs read 512 aligned
// 16KB windows at exact 512KB pitch — a phase-correlated address set that
// can transiently overload HBM channels (doc'd uniformity only 88-92%).
// Staggering spreads the instantaneous footprint over the whole 256MB.
// Output assignment and per-CTA summation order are fixed -> deterministic.

#define BB 16
#define NN 32
#define HH 64

__global__ __launch_bounds__(256, 4)
void msg_nn_kernel(const float4* __restrict__ W,
                   const float4* __restrict__ X,
                   float* __restrict__ out)
{
    const int bj = blockIdx.x;      // 0..511
    const int b  = bj >> 5;
    const int j  = bj & (NN - 1);

    __shared__ float4 xs[NN * HH / 4];   // x[b,:,:] = 512 float4 = 8 KB

    const int t = threadIdx.x;      // 0..255

    const float4* xb = X + (size_t)b * (NN * HH / 4);
    xs[t]       = xb[t];
    xs[t + 256] = xb[t + 256];
    __syncthreads();

    const int g4 = t & 15;
    const int h0 = t >> 4;

    const size_t tileF4 = (size_t)HH * HH / 4;        // 1024
    const size_t IS     = (size_t)NN * tileF4;        // 32768 f4 (i stride)
    const float4* Wbase = W + ((size_t)b * NN * NN + j) * tileF4 + t;

    const int istart = bj & (NN - 1);   // per-CTA phase stagger

    float acc0 = 0.f, acc1 = 0.f, acc2 = 0.f, acc3 = 0.f;

    #pragma unroll 2
    for (int k = 0; k < NN; ++k) {
        const int i = (k + istart) & (NN - 1);
        const float4* tp = Wbase + (size_t)i * IS;
        const float4 xv = xs[i * 16 + g4];

        const float4 w0 = tp[0];
        const float4 w1 = tp[256];
        const float4 w2 = tp[512];
        const float4 w3 = tp[768];

        acc0 += w0.x * xv.x + w0.y * xv.y + w0.z * xv.z + w0.w * xv.w;
        acc1 += w1.x * xv.x + w1.y * xv.y + w1.z * xv.z + w1.w * xv.w;
        acc2 += w2.x * xv.x + w2.y * xv.y + w2.z * xv.z + w2.w * xv.w;
        acc3 += w3.x * xv.x + w3.y * xv.y + w3.z * xv.z + w3.w * xv.w;
    }

    // Reduce 16 g-quads per h within each contiguous 16-lane group.
    const unsigned mask = 0xFFFFFFFFu;
    #pragma unroll
    for (int off = 8; off > 0; off >>= 1) {
        acc0 += __shfl_down_sync(mask, acc0, off);
        acc1 += __shfl_down_sync(mask, acc1, off);
        acc2 += __shfl_down_sync(mask, acc2, off);
        acc3 += __shfl_down_sync(mask, acc3, off);
    }

    if (g4 == 0) {
        const float sc = 1.0f / (float)NN;
        float* o = out + (size_t)bj * HH + h0;
        __stwt(o +  0, acc0 * sc);
        __stwt(o + 16, acc1 * sc);
        __stwt(o + 32, acc2 * sc);
        __stwt(o + 48, acc3 * sc);
    }
}

extern "C" void kernel_launch(void* const* d_in, const int* in_sizes, int n_in,
                              void* d_out, int out_size)
{
    const float4* W = (const float4*)d_in[0];   // edge_wgt [B,N,N,H,H] fp32
    const float4* X = (const float4*)d_in[1];   // node_hidden [B,N,H] fp32
    float* out = (float*)d_out;                 // [B,N,H] fp32

    msg_nn_kernel<<<BB * NN, 256>>>(W, X, out);   // 512 CTAs
}